// round 7
// baseline (speedup 1.0000x reference)
#include <cuda_runtime.h>
#include <cuda_bf16.h>
#include <math.h>
#include <stdint.h>

#define NMAX 50048
#define EMAX 1000000
#define F 128
#define LN_EPS 1e-5f

// ---------------------------------------------------------------------------
// Scratch (device globals — no allocation allowed)
__device__ float g_XA[NMAX * F];
__device__ float g_XB[NMAX * F];
__device__ float g_AGGS[NMAX * F];
__device__ float g_DEG[NMAX];
__device__ float g_V[F];
__device__ float g_C0;
__device__ int   g_IS64;
__device__ int   g_CNT[NMAX];
__device__ int   g_BASE[NMAX + 1];
__device__ int   g_RUN[NMAX];
__device__ int   g_SCOL[EMAX];

// ---------------------------------------------------------------------------
#define FFMA2(acc, a, b) \
    asm("fma.rn.f32x2 %0, %1, %2, %0;" : "+l"(acc) : "l"(a), "l"(b))
__device__ __forceinline__ unsigned long long pack2(float v) {
    unsigned long long r;
    unsigned int u = __float_as_uint(v);
    asm("mov.b64 %0, {%1, %1};" : "=l"(r) : "r"(u));
    return r;
}
__device__ __forceinline__ void unpack2(unsigned long long p, float& lo, float& hi) {
    unsigned int a, b;
    asm("mov.b64 {%0, %1}, %2;" : "=r"(a), "=r"(b) : "l"(p));
    lo = __uint_as_float(a);
    hi = __uint_as_float(b);
}
__device__ __forceinline__ uint32_t smem_u32(const void* p) {
    uint32_t a;
    asm("{ .reg .u64 t; cvta.to.shared.u64 t, %1; cvt.u32.u64 %0, t; }"
        : "=r"(a) : "l"(p));
    return a;
}
#define CP_ASYNC16(dst, src) \
    asm volatile("cp.async.cg.shared.global [%0], [%1], 16;" :: "r"(dst), "l"(src))
#define CP_COMMIT() asm volatile("cp.async.commit_group;" ::: "memory")
#define CP_WAIT0()  asm volatile("cp.async.wait_group 0;" ::: "memory")

// ---------------------------------------------------------------------------
__global__ void detect_kernel(const void* ei, int E, int N) {
    if (blockIdx.x == 0 && threadIdx.x == 0) {
        const long long* p = (const long long*)ei;
        int cnt = (2 * E < 256) ? 2 * E : 256;
        int ok = 1;
        for (int i = 0; i < cnt; i++) {
            long long v = p[i];
            if (v < 0 || v >= N) { ok = 0; break; }
        }
        g_IS64 = ok;
    }
}

__global__ void prep_vc(const float* __restrict__ ew2, const float* __restrict__ cw,
                        const float* __restrict__ eb2, const float* __restrict__ cb) {
    int t = threadIdx.x;
    float s = 0.f;
    for (int o = 0; o < F; o++) s += ew2[t * F + o] * cw[o];
    g_V[t] = s;
    if (t == 0) {
        float c = cb[0];
        for (int o = 0; o < F; o++) c += eb2[o] * cw[o];
        g_C0 = c;
    }
}

// ---------------------------------------------------------------------------
// CSR build: zero counters -> histogram -> scan -> scatter cols
__global__ void zero_cnt(int N) {
    int i = blockIdx.x * blockDim.x + threadIdx.x;
    if (i < N) g_CNT[i] = 0;
}

__global__ void hist_kernel(const void* __restrict__ ei_raw, int E) {
    int i = blockIdx.x * blockDim.x + threadIdx.x;
    if (i >= E) return;
    int row = g_IS64 ? (int)((const long long*)ei_raw)[i] : ((const int*)ei_raw)[i];
    atomicAdd(&g_CNT[row], 1);
}

__global__ void scan_kernel(int N) {
    __shared__ int part[1024];
    int tid = threadIdx.x;
    int chunk = (N + 1023) / 1024;
    int lo = tid * chunk;
    int hi = lo + chunk < N ? lo + chunk : N;
    int s = 0;
    for (int i = lo; i < hi; i++) s += g_CNT[i];
    part[tid] = s;
    __syncthreads();
    for (int o = 1; o < 1024; o <<= 1) {
        int u = (tid >= o) ? part[tid - o] : 0;
        __syncthreads();
        part[tid] += u;
        __syncthreads();
    }
    int run = (tid == 0) ? 0 : part[tid - 1];
    for (int i = lo; i < hi; i++) {
        g_BASE[i] = run;
        g_RUN[i] = run;
        run += g_CNT[i];
    }
    if (tid == 0) g_BASE[N] = part[1023];
}

__global__ void scatter_kernel(const void* __restrict__ ei_raw, int E) {
    int i = blockIdx.x * blockDim.x + threadIdx.x;
    if (i >= E) return;
    int row, col;
    if (g_IS64) {
        const long long* ei = (const long long*)ei_raw;
        row = (int)ei[i];
        col = (int)ei[(size_t)E + i];
    } else {
        const int* ei = (const int*)ei_raw;
        row = ei[i];
        col = ei[E + i];
    }
    int p = atomicAdd(&g_RUN[row], 1);
    g_SCOL[p] = col;
}

// ---------------------------------------------------------------------------
// Gather kernel: one warp per destination row.
// agg[r] = sum_e silu(XA[r] + XB[col_e] + d2_e * w)   (written once, no atomics)
// pout[r] = pos[r] + sum_e tanh(s_e . V + C0) * diff_e
// DEG[r]  = degree
__global__ void __launch_bounds__(256)
gather_kernel(const float* __restrict__ pos, const float* __restrict__ ew1,
              float* __restrict__ pout, int N) {
    int r = blockIdx.x * 8 + (threadIdx.x >> 5);
    int lane = threadIdx.x & 31;
    if (r >= N) return;

    int base = g_BASE[r], end = g_BASE[r + 1];

    float4 xa = ((const float4*)g_XA)[(size_t)r * 32 + lane];
    float4 w = __ldg((const float4*)(ew1 + 256 * F) + lane);
    float4 vv = ((const float4*)g_V)[lane];
    float px = __ldg(&pos[r * 3 + 0]);
    float py = __ldg(&pos[r * 3 + 1]);
    float pz = __ldg(&pos[r * 3 + 2]);

    float4 acc = make_float4(0.f, 0.f, 0.f, 0.f);
    float dax = 0.f, day = 0.f, daz = 0.f;
    float c0 = g_C0;

    for (int i = base; i < end; i++) {
        int c = g_SCOL[i];
        float4 xb = ((const float4*)g_XB)[(size_t)c * 32 + lane];
        float dx = px - __ldg(&pos[c * 3 + 0]);
        float dy = py - __ldg(&pos[c * 3 + 1]);
        float dz = pz - __ldg(&pos[c * 3 + 2]);
        float d2 = dx * dx + dy * dy + dz * dz;

        float p0 = xa.x + xb.x + d2 * w.x;
        float p1 = xa.y + xb.y + d2 * w.y;
        float p2 = xa.z + xb.z + d2 * w.z;
        float p3 = xa.w + xb.w + d2 * w.w;

        float s0 = p0 / (1.f + __expf(-p0));
        float s1 = p1 / (1.f + __expf(-p1));
        float s2 = p2 / (1.f + __expf(-p2));
        float s3 = p3 / (1.f + __expf(-p3));

        acc.x += s0; acc.y += s1; acc.z += s2; acc.w += s3;

        float d = s0 * vv.x + s1 * vv.y + s2 * vv.z + s3 * vv.w;
#pragma unroll
        for (int o = 16; o > 0; o >>= 1) d += __shfl_xor_sync(0xffffffffu, d, o);

        float sc = tanhf(d + c0);
        dax += sc * dx; day += sc * dy; daz += sc * dz;
    }

    ((float4*)g_AGGS)[(size_t)r * 32 + lane] = acc;
    if (lane == 0) {
        g_DEG[r] = (float)(end - base);
        pout[r * 3 + 0] = px + dax;
        pout[r * 3 + 1] = py + day;
        pout[r * 3 + 2] = pz + daz;
    }
}

// ---------------------------------------------------------------------------
// Pipelined register-tiled GEMM (unchanged from R6)
#define AS_STRIDE 132
#define WS_BYTES  16384
#define AS_BYTES  16896
#define SM_AS0    (2 * WS_BYTES)
#define SM_RT_TOTAL (2 * WS_BYTES + 2 * AS_BYTES)

template <int ACT>
__global__ void __launch_bounds__(256, 2)
gemm_rt(const float* __restrict__ A,
        const float* __restrict__ W0, const float* __restrict__ bias0,
        float* __restrict__ out0,
        const float* __restrict__ W1, const float* __restrict__ bias1,
        float* __restrict__ out1,
        const float* __restrict__ deg, const float* __restrict__ degvec, int N) {
    extern __shared__ char smem[];

    const float* W = W0;
    const float* bias = bias0;
    float* out = out0;
    if (blockIdx.y == 1) { W = W1; bias = bias1; out = out1; }

    int t = threadIdx.x;
    int lane = t & 31, w = t >> 5;
    int txl = lane & 3, tyl = lane >> 2;
    int wx = w & 3, wy = w >> 2;
    int col0 = (wx * 4 + txl) * 8;
    int rowt = (wy * 8 + tyl) * 8;
    int row0 = blockIdx.x * 128;

    uint32_t sb = smem_u32(smem);

    int arl = (w & 3) * 32 + lane;
    int kh  = (w >> 2) * 16;
    int arow = row0 + arl;
    const float4* Abase = (const float4*)(A + (size_t)arow * F);

    int wk = t >> 3, wcol = (t & 7) * 16;

    unsigned long long acc[8][4];
#pragma unroll
    for (int r = 0; r < 8; r++)
#pragma unroll
        for (int c = 0; c < 4; c++) acc[r][c] = 0ull;

    float4 v[4];

    {
        const float* wsrc = W + (size_t)wk * F + wcol;
        uint32_t wdst = sb + (uint32_t)(wk * F + wcol) * 4;
#pragma unroll
        for (int q = 0; q < 4; q++) CP_ASYNC16(wdst + q * 16, wsrc + q * 4);
        CP_COMMIT();
        if (arow < N) {
#pragma unroll
            for (int q = 0; q < 4; q++) v[q] = __ldg(&Abase[(kh >> 2) + q]);
        } else {
#pragma unroll
            for (int q = 0; q < 4; q++) v[q] = make_float4(0.f, 0.f, 0.f, 0.f);
        }
        float* As0 = (float*)(smem + SM_AS0);
#pragma unroll
        for (int q = 0; q < 4; q++) {
            float vals[4] = {v[q].x, v[q].y, v[q].z, v[q].w};
#pragma unroll
            for (int e = 0; e < 4; e++)
                As0[(kh + q * 4 + e) * AS_STRIDE + arl] = vals[e];
        }
        CP_WAIT0();
    }
    __syncthreads();

#pragma unroll 1
    for (int c = 0; c < 4; c++) {
        int cb = c & 1, nb = (c + 1) & 1;
        float* Ws = (float*)(smem + cb * WS_BYTES);
        float* As = (float*)(smem + SM_AS0 + cb * AS_BYTES);

        if (c < 3) {
            const float* wsrc = W + (size_t)((c + 1) * 32 + wk) * F + wcol;
            uint32_t wdst = sb + (uint32_t)nb * WS_BYTES + (uint32_t)(wk * F + wcol) * 4;
#pragma unroll
            for (int q = 0; q < 4; q++) CP_ASYNC16(wdst + q * 16, wsrc + q * 4);
            CP_COMMIT();
            if (arow < N) {
                int kb = ((c + 1) * 32 + kh) >> 2;
#pragma unroll
                for (int q = 0; q < 4; q++) v[q] = __ldg(&Abase[kb + q]);
            }
        }

#pragma unroll
        for (int kk = 0; kk < 32; kk++) {
            float4 al = *(const float4*)&As[kk * AS_STRIDE + rowt];
            float4 ah = *(const float4*)&As[kk * AS_STRIDE + rowt + 4];
            unsigned long long a0 = pack2(al.x), a1 = pack2(al.y);
            unsigned long long a2 = pack2(al.z), a3 = pack2(al.w);
            unsigned long long a4 = pack2(ah.x), a5 = pack2(ah.y);
            unsigned long long a6 = pack2(ah.z), a7 = pack2(ah.w);
            ulonglong2 bv0 = *(const ulonglong2*)&Ws[kk * F + col0];
            ulonglong2 bv1 = *(const ulonglong2*)&Ws[kk * F + col0 + 4];
            FFMA2(acc[0][0], a0, bv0.x); FFMA2(acc[0][1], a0, bv0.y);
            FFMA2(acc[0][2], a0, bv1.x); FFMA2(acc[0][3], a0, bv1.y);
            FFMA2(acc[1][0], a1, bv0.x); FFMA2(acc[1][1], a1, bv0.y);
            FFMA2(acc[1][2], a1, bv1.x); FFMA2(acc[1][3], a1, bv1.y);
            FFMA2(acc[2][0], a2, bv0.x); FFMA2(acc[2][1], a2, bv0.y);
            FFMA2(acc[2][2], a2, bv1.x); FFMA2(acc[2][3], a2, bv1.y);
            FFMA2(acc[3][0], a3, bv0.x); FFMA2(acc[3][1], a3, bv0.y);
            FFMA2(acc[3][2], a3, bv1.x); FFMA2(acc[3][3], a3, bv1.y);
            FFMA2(acc[4][0], a4, bv0.x); FFMA2(acc[4][1], a4, bv0.y);
            FFMA2(acc[4][2], a4, bv1.x); FFMA2(acc[4][3], a4, bv1.y);
            FFMA2(acc[5][0], a5, bv0.x); FFMA2(acc[5][1], a5, bv0.y);
            FFMA2(acc[5][2], a5, bv1.x); FFMA2(acc[5][3], a5, bv1.y);
            FFMA2(acc[6][0], a6, bv0.x); FFMA2(acc[6][1], a6, bv0.y);
            FFMA2(acc[6][2], a6, bv1.x); FFMA2(acc[6][3], a6, bv1.y);
            FFMA2(acc[7][0], a7, bv0.x); FFMA2(acc[7][1], a7, bv0.y);
            FFMA2(acc[7][2], a7, bv1.x); FFMA2(acc[7][3], a7, bv1.y);
        }

        if (c < 3) {
            float* Asn = (float*)(smem + SM_AS0 + nb * AS_BYTES);
            if (arow >= N) {
#pragma unroll
                for (int q = 0; q < 4; q++) v[q] = make_float4(0.f, 0.f, 0.f, 0.f);
            }
#pragma unroll
            for (int q = 0; q < 4; q++) {
                float vals[4] = {v[q].x, v[q].y, v[q].z, v[q].w};
#pragma unroll
                for (int e = 0; e < 4; e++)
                    Asn[(kh + q * 4 + e) * AS_STRIDE + arl] = vals[e];
            }
            CP_WAIT0();
        }
        __syncthreads();
    }

    float bcol[8], dcol[8];
#pragma unroll
    for (int j = 0; j < 8; j++) {
        bcol[j] = bias ? __ldg(&bias[col0 + j]) : 0.f;
        dcol[j] = degvec ? __ldg(&degvec[col0 + j]) : 0.f;
    }
#pragma unroll
    for (int rr = 0; rr < 8; rr++) {
        int row = row0 + rowt + rr;
        if (row < N) {
            float dg = deg ? deg[row] : 0.f;
            float o[8];
#pragma unroll
            for (int cp = 0; cp < 4; cp++) unpack2(acc[rr][cp], o[2 * cp], o[2 * cp + 1]);
#pragma unroll
            for (int j = 0; j < 8; j++) {
                float vv2 = o[j] + bcol[j] + dg * dcol[j];
                if (ACT == 1) vv2 = vv2 / (1.f + __expf(-vv2));
                o[j] = vv2;
            }
            float4* op = (float4*)(out + (size_t)row * F + col0);
            op[0] = make_float4(o[0], o[1], o[2], o[3]);
            op[1] = make_float4(o[4], o[5], o[6], o[7]);
        }
    }
}

// ---------------------------------------------------------------------------
// Residual + LayerNorm: xout = LN(P + x)
__global__ void __launch_bounds__(256)
ln_kernel(const float* __restrict__ P, const float* __restrict__ x,
          const float* __restrict__ gamma, const float* __restrict__ beta,
          float* __restrict__ xout, int N) {
    int row = blockIdx.x * 8 + (threadIdx.x >> 5);
    int lane = threadIdx.x & 31;
    if (row >= N) return;
    float4 p = ((const float4*)P)[(size_t)row * 32 + lane];
    float4 xv = ((const float4*)x)[(size_t)row * 32 + lane];
    float4 pre = make_float4(p.x + xv.x, p.y + xv.y, p.z + xv.z, p.w + xv.w);
    float s = pre.x + pre.y + pre.z + pre.w;
    float s2 = pre.x * pre.x + pre.y * pre.y + pre.z * pre.z + pre.w * pre.w;
#pragma unroll
    for (int o = 16; o > 0; o >>= 1) {
        s  += __shfl_xor_sync(0xffffffffu, s, o);
        s2 += __shfl_xor_sync(0xffffffffu, s2, o);
    }
    float mean = s * (1.f / F);
    float ri = rsqrtf(s2 * (1.f / F) - mean * mean + LN_EPS);
    float4 g = ((const float4*)gamma)[lane];
    float4 b = ((const float4*)beta)[lane];
    float4 o;
    o.x = g.x * (pre.x - mean) * ri + b.x;
    o.y = g.y * (pre.y - mean) * ri + b.y;
    o.z = g.z * (pre.z - mean) * ri + b.z;
    o.w = g.w * (pre.w - mean) * ri + b.w;
    ((float4*)xout)[(size_t)row * 32 + lane] = o;
}

// ---------------------------------------------------------------------------
extern "C" void kernel_launch(void* const* d_in, const int* in_sizes, int n_in,
                              void* d_out, int out_size) {
    const float* x     = (const float*)d_in[0];
    const float* pos   = (const float*)d_in[1];
    const void*  ei    = d_in[2];
    const float* ew1   = (const float*)d_in[3];
    const float* eb1   = (const float*)d_in[4];
    const float* ew2   = (const float*)d_in[5];
    const float* eb2   = (const float*)d_in[6];
    const float* nw1   = (const float*)d_in[7];
    const float* nb1   = (const float*)d_in[8];
    const float* nw2   = (const float*)d_in[9];
    const float* nb2   = (const float*)d_in[10];
    const float* cw    = (const float*)d_in[11];
    const float* cb    = (const float*)d_in[12];
    const float* gamma = (const float*)d_in[13];
    const float* beta  = (const float*)d_in[14];

    int N = in_sizes[0] / F;
    int E = in_sizes[2] / 2;

    float* xout = (float*)d_out;
    float* pout = (float*)d_out + (size_t)N * F;

    float* XA;   cudaGetSymbolAddress((void**)&XA,   g_XA);
    float* XB;   cudaGetSymbolAddress((void**)&XB,   g_XB);
    float* AGGS; cudaGetSymbolAddress((void**)&AGGS, g_AGGS);
    float* DEG;  cudaGetSymbolAddress((void**)&DEG,  g_DEG);

    cudaFuncSetAttribute(gemm_rt<0>, cudaFuncAttributeMaxDynamicSharedMemorySize, SM_RT_TOTAL);
    cudaFuncSetAttribute(gemm_rt<1>, cudaFuncAttributeMaxDynamicSharedMemorySize, SM_RT_TOTAL);

    int tcb = (N + 127) / 128;
    int eb256 = (E + 255) / 256;

    detect_kernel<<<1, 32>>>(ei, E, N);
    prep_vc<<<1, 128>>>(ew2, cw, eb2, cb);

    // CSR build (independent of GEMMs)
    zero_cnt<<<(N + 255) / 256, 256>>>(N);
    hist_kernel<<<eb256, 256>>>(ei, E);
    scan_kernel<<<1, 1024>>>(N);
    scatter_kernel<<<eb256, 256>>>(ei, E);

    // XA = x @ W1a + eb1 AND XB = x @ W1b — one merged launch
    gemm_rt<0><<<dim3(tcb, 2), 256, SM_RT_TOTAL>>>(
        x, ew1, eb1, XA, ew1 + 128 * F, nullptr, XB, nullptr, nullptr, N);

    // Gather: agg rows + degree + pos_out (no atomics)
    gather_kernel<<<(N + 7) / 8, 256>>>(pos, ew1, pout, N);

    // AGG = AGGS @ ew2 + deg*eb2  -> XA
    gemm_rt<0><<<tcb, 256, SM_RT_TOTAL>>>(AGGS, ew2, nullptr, XA,
                                          nullptr, nullptr, nullptr, DEG, eb2, N);
    // H = silu(AGG @ nw1 + nb1)   -> XB
    gemm_rt<1><<<tcb, 256, SM_RT_TOTAL>>>(XA, nw1, nb1, XB,
                                          nullptr, nullptr, nullptr, nullptr, nullptr, N);
    // P = H @ nw2 + nb2           -> AGGS (reuse)
    gemm_rt<0><<<tcb, 256, SM_RT_TOTAL>>>(XB, nw2, nb2, AGGS,
                                          nullptr, nullptr, nullptr, nullptr, nullptr, N);
    // x_out = LN(x + P)
    ln_kernel<<<(N + 7) / 8, 256>>>(AGGS, x, gamma, beta, xout, N);
}

// round 8
// speedup vs baseline: 1.0604x; 1.0604x over previous
#include <cuda_runtime.h>
#include <cuda_bf16.h>
#include <math.h>
#include <stdint.h>

#define NMAX 50048
#define EMAX 1000000
#define F 128
#define LN_EPS 1e-5f

// ---------------------------------------------------------------------------
// Scratch (device globals — no allocation allowed)
__device__ float g_XA[NMAX * F];
__device__ float g_XB[NMAX * F];
__device__ float g_AGGS[NMAX * F];
__device__ float g_DEG[NMAX];
__device__ float g_V[F];
__device__ float g_C0;
__device__ int   g_IS64;
__device__ int   g_CNT[NMAX];
__device__ int   g_BASE[NMAX + 1];
__device__ int   g_RUN[NMAX];
__device__ int   g_SCOL[EMAX];

// ---------------------------------------------------------------------------
#define FFMA2(acc, a, b) \
    asm("fma.rn.f32x2 %0, %1, %2, %0;" : "+l"(acc) : "l"(a), "l"(b))
__device__ __forceinline__ unsigned long long pack2(float v) {
    unsigned long long r;
    unsigned int u = __float_as_uint(v);
    asm("mov.b64 %0, {%1, %1};" : "=l"(r) : "r"(u));
    return r;
}
__device__ __forceinline__ void unpack2(unsigned long long p, float& lo, float& hi) {
    unsigned int a, b;
    asm("mov.b64 {%0, %1}, %2;" : "=r"(a), "=r"(b) : "l"(p));
    lo = __uint_as_float(a);
    hi = __uint_as_float(b);
}
__device__ __forceinline__ uint32_t smem_u32(const void* p) {
    uint32_t a;
    asm("{ .reg .u64 t; cvta.to.shared.u64 t, %1; cvt.u32.u64 %0, t; }"
        : "=r"(a) : "l"(p));
    return a;
}
#define CP_ASYNC16(dst, src) \
    asm volatile("cp.async.cg.shared.global [%0], [%1], 16;" :: "r"(dst), "l"(src))
#define CP_COMMIT() asm volatile("cp.async.commit_group;" ::: "memory")
#define CP_WAIT0()  asm volatile("cp.async.wait_group 0;" ::: "memory")

__device__ __forceinline__ float fast_sigmoid(float p) {
    return __fdividef(1.f, 1.f + __expf(-p));
}

// ---------------------------------------------------------------------------
__global__ void detect_kernel(const void* ei, int E, int N) {
    if (blockIdx.x == 0 && threadIdx.x == 0) {
        const long long* p = (const long long*)ei;
        int cnt = (2 * E < 256) ? 2 * E : 256;
        int ok = 1;
        for (int i = 0; i < cnt; i++) {
            long long v = p[i];
            if (v < 0 || v >= N) { ok = 0; break; }
        }
        g_IS64 = ok;
    }
}

__global__ void prep_vc(const float* __restrict__ ew2, const float* __restrict__ cw,
                        const float* __restrict__ eb2, const float* __restrict__ cb) {
    int t = threadIdx.x;
    float s = 0.f;
    for (int o = 0; o < F; o++) s += ew2[t * F + o] * cw[o];
    g_V[t] = s;
    if (t == 0) {
        float c = cb[0];
        for (int o = 0; o < F; o++) c += eb2[o] * cw[o];
        g_C0 = c;
    }
}

// ---------------------------------------------------------------------------
// CSR build
__global__ void zero_cnt(int N) {
    int i = blockIdx.x * blockDim.x + threadIdx.x;
    if (i < N) g_CNT[i] = 0;
}

__global__ void hist_kernel(const void* __restrict__ ei_raw, int E) {
    int i = blockIdx.x * blockDim.x + threadIdx.x;
    if (i >= E) return;
    int row = g_IS64 ? (int)((const long long*)ei_raw)[i] : ((const int*)ei_raw)[i];
    atomicAdd(&g_CNT[row], 1);
}

__global__ void scan_kernel(int N) {
    __shared__ int part[1024];
    int tid = threadIdx.x;
    int chunk = (N + 1023) / 1024;
    int lo = tid * chunk;
    int hi = lo + chunk < N ? lo + chunk : N;
    int s = 0;
    for (int i = lo; i < hi; i++) s += g_CNT[i];
    part[tid] = s;
    __syncthreads();
    for (int o = 1; o < 1024; o <<= 1) {
        int u = (tid >= o) ? part[tid - o] : 0;
        __syncthreads();
        part[tid] += u;
        __syncthreads();
    }
    int run = (tid == 0) ? 0 : part[tid - 1];
    for (int i = lo; i < hi; i++) {
        g_BASE[i] = run;
        g_RUN[i] = run;
        run += g_CNT[i];
    }
    if (tid == 0) g_BASE[N] = part[1023];
}

__global__ void scatter_kernel(const void* __restrict__ ei_raw, int E) {
    int i = blockIdx.x * blockDim.x + threadIdx.x;
    if (i >= E) return;
    int row, col;
    if (g_IS64) {
        const long long* ei = (const long long*)ei_raw;
        row = (int)ei[i];
        col = (int)ei[(size_t)E + i];
    } else {
        const int* ei = (const int*)ei_raw;
        row = ei[i];
        col = ei[E + i];
    }
    int p = atomicAdd(&g_RUN[row], 1);
    g_SCOL[p] = col;
}

// ---------------------------------------------------------------------------
// Gather kernel: one warp per destination row, 4-edge groups.
// Loads/silu for the 4 edges are independent (pipelined); dot reductions are
// 4 interleaved shfl butterflies; tanh + coord accumulation deferred off-chain.
__global__ void __launch_bounds__(256)
gather_kernel(const float* __restrict__ pos, const float* __restrict__ ew1,
              float* __restrict__ pout, int N) {
    int r = blockIdx.x * 8 + (threadIdx.x >> 5);
    int lane = threadIdx.x & 31;
    if (r >= N) return;

    int base = g_BASE[r], end = g_BASE[r + 1];

    float4 xa = ((const float4*)g_XA)[(size_t)r * 32 + lane];
    float4 w = __ldg((const float4*)(ew1 + 256 * F) + lane);
    float4 vv = ((const float4*)g_V)[lane];
    float px = __ldg(&pos[r * 3 + 0]);
    float py = __ldg(&pos[r * 3 + 1]);
    float pz = __ldg(&pos[r * 3 + 2]);

    float4 acc = make_float4(0.f, 0.f, 0.f, 0.f);
    float dax = 0.f, day = 0.f, daz = 0.f;
    float c0 = g_C0;

    for (int i = base; i < end; i += 4) {
        int m = end - i;
        float df[4], dxs[4], dys[4], dzs[4];
#pragma unroll
        for (int j = 0; j < 4; j++) {
            df[j] = 0.f;
            dxs[j] = 0.f; dys[j] = 0.f; dzs[j] = 0.f;
            if (j < m) {
                int c = __ldg(&g_SCOL[i + j]);
                float4 xb = ((const float4*)g_XB)[(size_t)c * 32 + lane];
                float dx = px - __ldg(&pos[c * 3 + 0]);
                float dy = py - __ldg(&pos[c * 3 + 1]);
                float dz = pz - __ldg(&pos[c * 3 + 2]);
                float d2 = dx * dx + dy * dy + dz * dz;

                float p0 = xa.x + xb.x + d2 * w.x;
                float p1 = xa.y + xb.y + d2 * w.y;
                float p2 = xa.z + xb.z + d2 * w.z;
                float p3 = xa.w + xb.w + d2 * w.w;

                float s0 = p0 * fast_sigmoid(p0);
                float s1 = p1 * fast_sigmoid(p1);
                float s2 = p2 * fast_sigmoid(p2);
                float s3 = p3 * fast_sigmoid(p3);

                acc.x += s0; acc.y += s1; acc.z += s2; acc.w += s3;

                df[j] = s0 * vv.x + s1 * vv.y + s2 * vv.z + s3 * vv.w;
                dxs[j] = dx; dys[j] = dy; dzs[j] = dz;
            }
        }
        // 4 interleaved butterflies — 20 independent SHFLs, pipelined
#pragma unroll
        for (int o = 16; o > 0; o >>= 1) {
#pragma unroll
            for (int j = 0; j < 4; j++)
                df[j] += __shfl_xor_sync(0xffffffffu, df[j], o);
        }
#pragma unroll
        for (int j = 0; j < 4; j++) {
            float sc = tanhf(df[j] + c0);
            dax += sc * dxs[j];
            day += sc * dys[j];
            daz += sc * dzs[j];
        }
    }

    ((float4*)g_AGGS)[(size_t)r * 32 + lane] = acc;
    if (lane == 0) {
        g_DEG[r] = (float)(end - base);
        pout[r * 3 + 0] = px + dax;
        pout[r * 3 + 1] = py + day;
        pout[r * 3 + 2] = pz + daz;
    }
}

// ---------------------------------------------------------------------------
// Pipelined register-tiled GEMM (R6 structure; __fdividef silu)
#define AS_STRIDE 132
#define WS_BYTES  16384
#define AS_BYTES  16896
#define SM_AS0    (2 * WS_BYTES)
#define SM_RT_TOTAL (2 * WS_BYTES + 2 * AS_BYTES)

template <int ACT>
__global__ void __launch_bounds__(256, 2)
gemm_rt(const float* __restrict__ A,
        const float* __restrict__ W0, const float* __restrict__ bias0,
        float* __restrict__ out0,
        const float* __restrict__ W1, const float* __restrict__ bias1,
        float* __restrict__ out1,
        const float* __restrict__ deg, const float* __restrict__ degvec, int N) {
    extern __shared__ char smem[];

    const float* W = W0;
    const float* bias = bias0;
    float* out = out0;
    if (blockIdx.y == 1) { W = W1; bias = bias1; out = out1; }

    int t = threadIdx.x;
    int lane = t & 31, w = t >> 5;
    int txl = lane & 3, tyl = lane >> 2;
    int wx = w & 3, wy = w >> 2;
    int col0 = (wx * 4 + txl) * 8;
    int rowt = (wy * 8 + tyl) * 8;
    int row0 = blockIdx.x * 128;

    uint32_t sb = smem_u32(smem);

    int arl = (w & 3) * 32 + lane;
    int kh  = (w >> 2) * 16;
    int arow = row0 + arl;
    const float4* Abase = (const float4*)(A + (size_t)arow * F);

    int wk = t >> 3, wcol = (t & 7) * 16;

    unsigned long long acc[8][4];
#pragma unroll
    for (int r = 0; r < 8; r++)
#pragma unroll
        for (int c = 0; c < 4; c++) acc[r][c] = 0ull;

    float4 v[4];

    {
        const float* wsrc = W + (size_t)wk * F + wcol;
        uint32_t wdst = sb + (uint32_t)(wk * F + wcol) * 4;
#pragma unroll
        for (int q = 0; q < 4; q++) CP_ASYNC16(wdst + q * 16, wsrc + q * 4);
        CP_COMMIT();
        if (arow < N) {
#pragma unroll
            for (int q = 0; q < 4; q++) v[q] = __ldg(&Abase[(kh >> 2) + q]);
        } else {
#pragma unroll
            for (int q = 0; q < 4; q++) v[q] = make_float4(0.f, 0.f, 0.f, 0.f);
        }
        float* As0 = (float*)(smem + SM_AS0);
#pragma unroll
        for (int q = 0; q < 4; q++) {
            float vals[4] = {v[q].x, v[q].y, v[q].z, v[q].w};
#pragma unroll
            for (int e = 0; e < 4; e++)
                As0[(kh + q * 4 + e) * AS_STRIDE + arl] = vals[e];
        }
        CP_WAIT0();
    }
    __syncthreads();

#pragma unroll 1
    for (int c = 0; c < 4; c++) {
        int cb = c & 1, nb = (c + 1) & 1;
        float* Ws = (float*)(smem + cb * WS_BYTES);
        float* As = (float*)(smem + SM_AS0 + cb * AS_BYTES);

        if (c < 3) {
            const float* wsrc = W + (size_t)((c + 1) * 32 + wk) * F + wcol;
            uint32_t wdst = sb + (uint32_t)nb * WS_BYTES + (uint32_t)(wk * F + wcol) * 4;
#pragma unroll
            for (int q = 0; q < 4; q++) CP_ASYNC16(wdst + q * 16, wsrc + q * 4);
            CP_COMMIT();
            if (arow < N) {
                int kb = ((c + 1) * 32 + kh) >> 2;
#pragma unroll
                for (int q = 0; q < 4; q++) v[q] = __ldg(&Abase[kb + q]);
            }
        }

#pragma unroll
        for (int kk = 0; kk < 32; kk++) {
            float4 al = *(const float4*)&As[kk * AS_STRIDE + rowt];
            float4 ah = *(const float4*)&As[kk * AS_STRIDE + rowt + 4];
            unsigned long long a0 = pack2(al.x), a1 = pack2(al.y);
            unsigned long long a2 = pack2(al.z), a3 = pack2(al.w);
            unsigned long long a4 = pack2(ah.x), a5 = pack2(ah.y);
            unsigned long long a6 = pack2(ah.z), a7 = pack2(ah.w);
            ulonglong2 bv0 = *(const ulonglong2*)&Ws[kk * F + col0];
            ulonglong2 bv1 = *(const ulonglong2*)&Ws[kk * F + col0 + 4];
            FFMA2(acc[0][0], a0, bv0.x); FFMA2(acc[0][1], a0, bv0.y);
            FFMA2(acc[0][2], a0, bv1.x); FFMA2(acc[0][3], a0, bv1.y);
            FFMA2(acc[1][0], a1, bv0.x); FFMA2(acc[1][1], a1, bv0.y);
            FFMA2(acc[1][2], a1, bv1.x); FFMA2(acc[1][3], a1, bv1.y);
            FFMA2(acc[2][0], a2, bv0.x); FFMA2(acc[2][1], a2, bv0.y);
            FFMA2(acc[2][2], a2, bv1.x); FFMA2(acc[2][3], a2, bv1.y);
            FFMA2(acc[3][0], a3, bv0.x); FFMA2(acc[3][1], a3, bv0.y);
            FFMA2(acc[3][2], a3, bv1.x); FFMA2(acc[3][3], a3, bv1.y);
            FFMA2(acc[4][0], a4, bv0.x); FFMA2(acc[4][1], a4, bv0.y);
            FFMA2(acc[4][2], a4, bv1.x); FFMA2(acc[4][3], a4, bv1.y);
            FFMA2(acc[5][0], a5, bv0.x); FFMA2(acc[5][1], a5, bv0.y);
            FFMA2(acc[5][2], a5, bv1.x); FFMA2(acc[5][3], a5, bv1.y);
            FFMA2(acc[6][0], a6, bv0.x); FFMA2(acc[6][1], a6, bv0.y);
            FFMA2(acc[6][2], a6, bv1.x); FFMA2(acc[6][3], a6, bv1.y);
            FFMA2(acc[7][0], a7, bv0.x); FFMA2(acc[7][1], a7, bv0.y);
            FFMA2(acc[7][2], a7, bv1.x); FFMA2(acc[7][3], a7, bv1.y);
        }

        if (c < 3) {
            float* Asn = (float*)(smem + SM_AS0 + nb * AS_BYTES);
            if (arow >= N) {
#pragma unroll
                for (int q = 0; q < 4; q++) v[q] = make_float4(0.f, 0.f, 0.f, 0.f);
            }
#pragma unroll
            for (int q = 0; q < 4; q++) {
                float vals[4] = {v[q].x, v[q].y, v[q].z, v[q].w};
#pragma unroll
                for (int e = 0; e < 4; e++)
                    Asn[(kh + q * 4 + e) * AS_STRIDE + arl] = vals[e];
            }
            CP_WAIT0();
        }
        __syncthreads();
    }

    float bcol[8], dcol[8];
#pragma unroll
    for (int j = 0; j < 8; j++) {
        bcol[j] = bias ? __ldg(&bias[col0 + j]) : 0.f;
        dcol[j] = degvec ? __ldg(&degvec[col0 + j]) : 0.f;
    }
#pragma unroll
    for (int rr = 0; rr < 8; rr++) {
        int row = row0 + rowt + rr;
        if (row < N) {
            float dg = deg ? deg[row] : 0.f;
            float o[8];
#pragma unroll
            for (int cp = 0; cp < 4; cp++) unpack2(acc[rr][cp], o[2 * cp], o[2 * cp + 1]);
#pragma unroll
            for (int j = 0; j < 8; j++) {
                float vv2 = o[j] + bcol[j] + dg * dcol[j];
                if (ACT == 1) vv2 = vv2 * fast_sigmoid(vv2);
                o[j] = vv2;
            }
            float4* op = (float4*)(out + (size_t)row * F + col0);
            op[0] = make_float4(o[0], o[1], o[2], o[3]);
            op[1] = make_float4(o[4], o[5], o[6], o[7]);
        }
    }
}

// ---------------------------------------------------------------------------
// Residual + LayerNorm: xout = LN(P + x)
__global__ void __launch_bounds__(256)
ln_kernel(const float* __restrict__ P, const float* __restrict__ x,
          const float* __restrict__ gamma, const float* __restrict__ beta,
          float* __restrict__ xout, int N) {
    int row = blockIdx.x * 8 + (threadIdx.x >> 5);
    int lane = threadIdx.x & 31;
    if (row >= N) return;
    float4 p = ((const float4*)P)[(size_t)row * 32 + lane];
    float4 xv = ((const float4*)x)[(size_t)row * 32 + lane];
    float4 pre = make_float4(p.x + xv.x, p.y + xv.y, p.z + xv.z, p.w + xv.w);
    float s = pre.x + pre.y + pre.z + pre.w;
    float s2 = pre.x * pre.x + pre.y * pre.y + pre.z * pre.z + pre.w * pre.w;
#pragma unroll
    for (int o = 16; o > 0; o >>= 1) {
        s  += __shfl_xor_sync(0xffffffffu, s, o);
        s2 += __shfl_xor_sync(0xffffffffu, s2, o);
    }
    float mean = s * (1.f / F);
    float ri = rsqrtf(s2 * (1.f / F) - mean * mean + LN_EPS);
    float4 g = ((const float4*)gamma)[lane];
    float4 b = ((const float4*)beta)[lane];
    float4 o;
    o.x = g.x * (pre.x - mean) * ri + b.x;
    o.y = g.y * (pre.y - mean) * ri + b.y;
    o.z = g.z * (pre.z - mean) * ri + b.z;
    o.w = g.w * (pre.w - mean) * ri + b.w;
    ((float4*)xout)[(size_t)row * 32 + lane] = o;
}

// ---------------------------------------------------------------------------
extern "C" void kernel_launch(void* const* d_in, const int* in_sizes, int n_in,
                              void* d_out, int out_size) {
    const float* x     = (const float*)d_in[0];
    const float* pos   = (const float*)d_in[1];
    const void*  ei    = d_in[2];
    const float* ew1   = (const float*)d_in[3];
    const float* eb1   = (const float*)d_in[4];
    const float* ew2   = (const float*)d_in[5];
    const float* eb2   = (const float*)d_in[6];
    const float* nw1   = (const float*)d_in[7];
    const float* nb1   = (const float*)d_in[8];
    const float* nw2   = (const float*)d_in[9];
    const float* nb2   = (const float*)d_in[10];
    const float* cw    = (const float*)d_in[11];
    const float* cb    = (const float*)d_in[12];
    const float* gamma = (const float*)d_in[13];
    const float* beta  = (const float*)d_in[14];

    int N = in_sizes[0] / F;
    int E = in_sizes[2] / 2;

    float* xout = (float*)d_out;
    float* pout = (float*)d_out + (size_t)N * F;

    float* XA;   cudaGetSymbolAddress((void**)&XA,   g_XA);
    float* XB;   cudaGetSymbolAddress((void**)&XB,   g_XB);
    float* AGGS; cudaGetSymbolAddress((void**)&AGGS, g_AGGS);
    float* DEG;  cudaGetSymbolAddress((void**)&DEG,  g_DEG);

    cudaFuncSetAttribute(gemm_rt<0>, cudaFuncAttributeMaxDynamicSharedMemorySize, SM_RT_TOTAL);
    cudaFuncSetAttribute(gemm_rt<1>, cudaFuncAttributeMaxDynamicSharedMemorySize, SM_RT_TOTAL);

    int tcb = (N + 127) / 128;
    int eb256 = (E + 255) / 256;

    detect_kernel<<<1, 32>>>(ei, E, N);
    prep_vc<<<1, 128>>>(ew2, cw, eb2, cb);

    // CSR build (independent of GEMMs)
    zero_cnt<<<(N + 255) / 256, 256>>>(N);
    hist_kernel<<<eb256, 256>>>(ei, E);
    scan_kernel<<<1, 1024>>>(N);
    scatter_kernel<<<eb256, 256>>>(ei, E);

    // XA = x @ W1a + eb1 AND XB = x @ W1b — one merged launch
    gemm_rt<0><<<dim3(tcb, 2), 256, SM_RT_TOTAL>>>(
        x, ew1, eb1, XA, ew1 + 128 * F, nullptr, XB, nullptr, nullptr, N);

    // Gather: agg rows + degree + pos_out (no atomics)
    gather_kernel<<<(N + 7) / 8, 256>>>(pos, ew1, pout, N);

    // AGG = AGGS @ ew2 + deg*eb2  -> XA
    gemm_rt<0><<<tcb, 256, SM_RT_TOTAL>>>(AGGS, ew2, nullptr, XA,
                                          nullptr, nullptr, nullptr, DEG, eb2, N);
    // H = silu(AGG @ nw1 + nb1)   -> XB
    gemm_rt<1><<<tcb, 256, SM_RT_TOTAL>>>(XA, nw1, nb1, XB,
                                          nullptr, nullptr, nullptr, nullptr, nullptr, N);
    // P = H @ nw2 + nb2           -> AGGS (reuse)
    gemm_rt<0><<<tcb, 256, SM_RT_TOTAL>>>(XB, nw2, nb2, AGGS,
                                          nullptr, nullptr, nullptr, nullptr, nullptr, N);
    // x_out = LN(x + P)
    ln_kernel<<<(N + 7) / 8, 256>>>(AGGS, x, gamma, beta, xout, N);
}

// round 9
// speedup vs baseline: 1.0626x; 1.0021x over previous
#include <cuda_runtime.h>
#include <cuda_bf16.h>
#include <math.h>
#include <stdint.h>

#define NMAX 50048
#define EMAX 1000000
#define F 128
#define LN_EPS 1e-5f

// ---------------------------------------------------------------------------
// Scratch (device globals — no allocation allowed)
__device__ float g_XA[NMAX * F];
__device__ float g_XB[NMAX * F];
__device__ float g_AGGS[NMAX * F];
__device__ float g_DEG[NMAX];
__device__ float g_V[F];
__device__ float g_C0;
__device__ int   g_IS64;
__device__ int   g_CNT[NMAX];
__device__ int   g_BASE[NMAX + 1];
__device__ int   g_RUN[NMAX];
__device__ int   g_SCOL[EMAX];

// ---------------------------------------------------------------------------
#define FFMA2(acc, a, b) \
    asm("fma.rn.f32x2 %0, %1, %2, %0;" : "+l"(acc) : "l"(a), "l"(b))
__device__ __forceinline__ unsigned long long pack2(float v) {
    unsigned long long r;
    unsigned int u = __float_as_uint(v);
    asm("mov.b64 %0, {%1, %1};" : "=l"(r) : "r"(u));
    return r;
}
__device__ __forceinline__ void unpack2(unsigned long long p, float& lo, float& hi) {
    unsigned int a, b;
    asm("mov.b64 {%0, %1}, %2;" : "=r"(a), "=r"(b) : "l"(p));
    lo = __uint_as_float(a);
    hi = __uint_as_float(b);
}
__device__ __forceinline__ uint32_t smem_u32(const void* p) {
    uint32_t a;
    asm("{ .reg .u64 t; cvta.to.shared.u64 t, %1; cvt.u32.u64 %0, t; }"
        : "=r"(a) : "l"(p));
    return a;
}
#define CP_ASYNC16(dst, src) \
    asm volatile("cp.async.cg.shared.global [%0], [%1], 16;" :: "r"(dst), "l"(src))
#define CP_COMMIT() asm volatile("cp.async.commit_group;" ::: "memory")
#define CP_WAIT0()  asm volatile("cp.async.wait_group 0;" ::: "memory")

__device__ __forceinline__ float fast_sigmoid(float p) {
    return __fdividef(1.f, 1.f + __expf(-p));
}

// ---------------------------------------------------------------------------
// Parallel dtype detect: 256 independent loads + flag OR (was 1-thread serial).
__global__ void detect_kernel(const void* ei, int E, int N) {
    __shared__ int bad;
    if (threadIdx.x == 0) bad = 0;
    __syncthreads();
    int cnt = (2 * E < 256) ? 2 * E : 256;
    if ((int)threadIdx.x < cnt) {
        long long v = ((const long long*)ei)[threadIdx.x];
        if (v < 0 || v >= N) bad = 1;
    }
    __syncthreads();
    if (threadIdx.x == 0) g_IS64 = !bad;
}

__global__ void prep_vc(const float* __restrict__ ew2, const float* __restrict__ cw,
                        const float* __restrict__ eb2, const float* __restrict__ cb) {
    int t = threadIdx.x;
    float s = 0.f;
    for (int o = 0; o < F; o++) s += ew2[t * F + o] * cw[o];
    g_V[t] = s;
    if (t == 0) {
        float c = cb[0];
        for (int o = 0; o < F; o++) c += eb2[o] * cw[o];
        g_C0 = c;
    }
}

// ---------------------------------------------------------------------------
// CSR build
__global__ void zero_cnt(int N) {
    int i = blockIdx.x * blockDim.x + threadIdx.x;
    if (i < N) g_CNT[i] = 0;
}

__global__ void hist_kernel(const void* __restrict__ ei_raw, int E) {
    int i = blockIdx.x * blockDim.x + threadIdx.x;
    if (i >= E) return;
    int row = g_IS64 ? (int)((const long long*)ei_raw)[i] : ((const int*)ei_raw)[i];
    atomicAdd(&g_CNT[row], 1);
}

__global__ void scan_kernel(int N) {
    __shared__ int part[1024];
    int tid = threadIdx.x;
    int chunk = (N + 1023) / 1024;
    int lo = tid * chunk;
    int hi = lo + chunk < N ? lo + chunk : N;
    int s = 0;
    for (int i = lo; i < hi; i++) s += g_CNT[i];
    part[tid] = s;
    __syncthreads();
    for (int o = 1; o < 1024; o <<= 1) {
        int u = (tid >= o) ? part[tid - o] : 0;
        __syncthreads();
        part[tid] += u;
        __syncthreads();
    }
    int run = (tid == 0) ? 0 : part[tid - 1];
    for (int i = lo; i < hi; i++) {
        g_BASE[i] = run;
        g_RUN[i] = run;
        run += g_CNT[i];
    }
    if (tid == 0) g_BASE[N] = part[1023];
}

__global__ void scatter_kernel(const void* __restrict__ ei_raw, int E) {
    int i = blockIdx.x * blockDim.x + threadIdx.x;
    if (i >= E) return;
    int row, col;
    if (g_IS64) {
        const long long* ei = (const long long*)ei_raw;
        row = (int)ei[i];
        col = (int)ei[(size_t)E + i];
    } else {
        const int* ei = (const int*)ei_raw;
        row = ei[i];
        col = ei[E + i];
    }
    int p = atomicAdd(&g_RUN[row], 1);
    g_SCOL[p] = col;
}

// ---------------------------------------------------------------------------
// Gather kernel: one warp per destination row, 4-edge groups, with SCOL
// prefetched one group ahead (kills the idx->XB two-level latency chain).
__global__ void __launch_bounds__(256)
gather_kernel(const float* __restrict__ pos, const float* __restrict__ ew1,
              float* __restrict__ pout, int N) {
    int r = blockIdx.x * 8 + (threadIdx.x >> 5);
    int lane = threadIdx.x & 31;
    if (r >= N) return;

    int base = g_BASE[r], end = g_BASE[r + 1];

    float4 xa = ((const float4*)g_XA)[(size_t)r * 32 + lane];
    float4 w = __ldg((const float4*)(ew1 + 256 * F) + lane);
    float4 vv = ((const float4*)g_V)[lane];
    float px = __ldg(&pos[r * 3 + 0]);
    float py = __ldg(&pos[r * 3 + 1]);
    float pz = __ldg(&pos[r * 3 + 2]);

    float4 acc = make_float4(0.f, 0.f, 0.f, 0.f);
    float dax = 0.f, day = 0.f, daz = 0.f;
    float c0 = g_C0;

    int nxt[4];
#pragma unroll
    for (int j = 0; j < 4; j++)
        nxt[j] = (base + j < end) ? __ldg(&g_SCOL[base + j]) : -1;

    for (int i = base; i < end; i += 4) {
        int cur[4];
#pragma unroll
        for (int j = 0; j < 4; j++) cur[j] = nxt[j];
        // prefetch indices for the NEXT group (in flight under this group's work)
#pragma unroll
        for (int j = 0; j < 4; j++)
            nxt[j] = (i + 4 + j < end) ? __ldg(&g_SCOL[i + 4 + j]) : -1;

        float df[4], dxs[4], dys[4], dzs[4];
#pragma unroll
        for (int j = 0; j < 4; j++) {
            df[j] = 0.f;
            dxs[j] = 0.f; dys[j] = 0.f; dzs[j] = 0.f;
            int c = cur[j];
            if (c >= 0) {
                float4 xb = ((const float4*)g_XB)[(size_t)c * 32 + lane];
                float dx = px - __ldg(&pos[c * 3 + 0]);
                float dy = py - __ldg(&pos[c * 3 + 1]);
                float dz = pz - __ldg(&pos[c * 3 + 2]);
                float d2 = dx * dx + dy * dy + dz * dz;

                float p0 = xa.x + xb.x + d2 * w.x;
                float p1 = xa.y + xb.y + d2 * w.y;
                float p2 = xa.z + xb.z + d2 * w.z;
                float p3 = xa.w + xb.w + d2 * w.w;

                float s0 = p0 * fast_sigmoid(p0);
                float s1 = p1 * fast_sigmoid(p1);
                float s2 = p2 * fast_sigmoid(p2);
                float s3 = p3 * fast_sigmoid(p3);

                acc.x += s0; acc.y += s1; acc.z += s2; acc.w += s3;

                df[j] = s0 * vv.x + s1 * vv.y + s2 * vv.z + s3 * vv.w;
                dxs[j] = dx; dys[j] = dy; dzs[j] = dz;
            }
        }
        // 4 interleaved butterflies — 20 independent SHFLs, pipelined
#pragma unroll
        for (int o = 16; o > 0; o >>= 1) {
#pragma unroll
            for (int j = 0; j < 4; j++)
                df[j] += __shfl_xor_sync(0xffffffffu, df[j], o);
        }
#pragma unroll
        for (int j = 0; j < 4; j++) {
            float sc = tanhf(df[j] + c0);
            dax += sc * dxs[j];
            day += sc * dys[j];
            daz += sc * dzs[j];
        }
    }

    ((float4*)g_AGGS)[(size_t)r * 32 + lane] = acc;
    if (lane == 0) {
        g_DEG[r] = (float)(end - base);
        pout[r * 3 + 0] = px + dax;
        pout[r * 3 + 1] = py + day;
        pout[r * 3 + 2] = pz + daz;
    }
}

// ---------------------------------------------------------------------------
// Pipelined register-tiled GEMM (R6 structure; __fdividef silu)
#define AS_STRIDE 132
#define WS_BYTES  16384
#define AS_BYTES  16896
#define SM_AS0    (2 * WS_BYTES)
#define SM_RT_TOTAL (2 * WS_BYTES + 2 * AS_BYTES)

template <int ACT>
__global__ void __launch_bounds__(256, 2)
gemm_rt(const float* __restrict__ A,
        const float* __restrict__ W0, const float* __restrict__ bias0,
        float* __restrict__ out0,
        const float* __restrict__ W1, const float* __restrict__ bias1,
        float* __restrict__ out1,
        const float* __restrict__ deg, const float* __restrict__ degvec, int N) {
    extern __shared__ char smem[];

    const float* W = W0;
    const float* bias = bias0;
    float* out = out0;
    if (blockIdx.y == 1) { W = W1; bias = bias1; out = out1; }

    int t = threadIdx.x;
    int lane = t & 31, w = t >> 5;
    int txl = lane & 3, tyl = lane >> 2;
    int wx = w & 3, wy = w >> 2;
    int col0 = (wx * 4 + txl) * 8;
    int rowt = (wy * 8 + tyl) * 8;
    int row0 = blockIdx.x * 128;

    uint32_t sb = smem_u32(smem);

    int arl = (w & 3) * 32 + lane;
    int kh  = (w >> 2) * 16;
    int arow = row0 + arl;
    const float4* Abase = (const float4*)(A + (size_t)arow * F);

    int wk = t >> 3, wcol = (t & 7) * 16;

    unsigned long long acc[8][4];
#pragma unroll
    for (int r = 0; r < 8; r++)
#pragma unroll
        for (int c = 0; c < 4; c++) acc[r][c] = 0ull;

    float4 v[4];

    {
        const float* wsrc = W + (size_t)wk * F + wcol;
        uint32_t wdst = sb + (uint32_t)(wk * F + wcol) * 4;
#pragma unroll
        for (int q = 0; q < 4; q++) CP_ASYNC16(wdst + q * 16, wsrc + q * 4);
        CP_COMMIT();
        if (arow < N) {
#pragma unroll
            for (int q = 0; q < 4; q++) v[q] = __ldg(&Abase[(kh >> 2) + q]);
        } else {
#pragma unroll
            for (int q = 0; q < 4; q++) v[q] = make_float4(0.f, 0.f, 0.f, 0.f);
        }
        float* As0 = (float*)(smem + SM_AS0);
#pragma unroll
        for (int q = 0; q < 4; q++) {
            float vals[4] = {v[q].x, v[q].y, v[q].z, v[q].w};
#pragma unroll
            for (int e = 0; e < 4; e++)
                As0[(kh + q * 4 + e) * AS_STRIDE + arl] = vals[e];
        }
        CP_WAIT0();
    }
    __syncthreads();

#pragma unroll 1
    for (int c = 0; c < 4; c++) {
        int cb = c & 1, nb = (c + 1) & 1;
        float* Ws = (float*)(smem + cb * WS_BYTES);
        float* As = (float*)(smem + SM_AS0 + cb * AS_BYTES);

        if (c < 3) {
            const float* wsrc = W + (size_t)((c + 1) * 32 + wk) * F + wcol;
            uint32_t wdst = sb + (uint32_t)nb * WS_BYTES + (uint32_t)(wk * F + wcol) * 4;
#pragma unroll
            for (int q = 0; q < 4; q++) CP_ASYNC16(wdst + q * 16, wsrc + q * 4);
            CP_COMMIT();
            if (arow < N) {
                int kb = ((c + 1) * 32 + kh) >> 2;
#pragma unroll
                for (int q = 0; q < 4; q++) v[q] = __ldg(&Abase[kb + q]);
            }
        }

#pragma unroll
        for (int kk = 0; kk < 32; kk++) {
            float4 al = *(const float4*)&As[kk * AS_STRIDE + rowt];
            float4 ah = *(const float4*)&As[kk * AS_STRIDE + rowt + 4];
            unsigned long long a0 = pack2(al.x), a1 = pack2(al.y);
            unsigned long long a2 = pack2(al.z), a3 = pack2(al.w);
            unsigned long long a4 = pack2(ah.x), a5 = pack2(ah.y);
            unsigned long long a6 = pack2(ah.z), a7 = pack2(ah.w);
            ulonglong2 bv0 = *(const ulonglong2*)&Ws[kk * F + col0];
            ulonglong2 bv1 = *(const ulonglong2*)&Ws[kk * F + col0 + 4];
            FFMA2(acc[0][0], a0, bv0.x); FFMA2(acc[0][1], a0, bv0.y);
            FFMA2(acc[0][2], a0, bv1.x); FFMA2(acc[0][3], a0, bv1.y);
            FFMA2(acc[1][0], a1, bv0.x); FFMA2(acc[1][1], a1, bv0.y);
            FFMA2(acc[1][2], a1, bv1.x); FFMA2(acc[1][3], a1, bv1.y);
            FFMA2(acc[2][0], a2, bv0.x); FFMA2(acc[2][1], a2, bv0.y);
            FFMA2(acc[2][2], a2, bv1.x); FFMA2(acc[2][3], a2, bv1.y);
            FFMA2(acc[3][0], a3, bv0.x); FFMA2(acc[3][1], a3, bv0.y);
            FFMA2(acc[3][2], a3, bv1.x); FFMA2(acc[3][3], a3, bv1.y);
            FFMA2(acc[4][0], a4, bv0.x); FFMA2(acc[4][1], a4, bv0.y);
            FFMA2(acc[4][2], a4, bv1.x); FFMA2(acc[4][3], a4, bv1.y);
            FFMA2(acc[5][0], a5, bv0.x); FFMA2(acc[5][1], a5, bv0.y);
            FFMA2(acc[5][2], a5, bv1.x); FFMA2(acc[5][3], a5, bv1.y);
            FFMA2(acc[6][0], a6, bv0.x); FFMA2(acc[6][1], a6, bv0.y);
            FFMA2(acc[6][2], a6, bv1.x); FFMA2(acc[6][3], a6, bv1.y);
            FFMA2(acc[7][0], a7, bv0.x); FFMA2(acc[7][1], a7, bv0.y);
            FFMA2(acc[7][2], a7, bv1.x); FFMA2(acc[7][3], a7, bv1.y);
        }

        if (c < 3) {
            float* Asn = (float*)(smem + SM_AS0 + nb * AS_BYTES);
            if (arow >= N) {
#pragma unroll
                for (int q = 0; q < 4; q++) v[q] = make_float4(0.f, 0.f, 0.f, 0.f);
            }
#pragma unroll
            for (int q = 0; q < 4; q++) {
                float vals[4] = {v[q].x, v[q].y, v[q].z, v[q].w};
#pragma unroll
                for (int e = 0; e < 4; e++)
                    Asn[(kh + q * 4 + e) * AS_STRIDE + arl] = vals[e];
            }
            CP_WAIT0();
        }
        __syncthreads();
    }

    float bcol[8], dcol[8];
#pragma unroll
    for (int j = 0; j < 8; j++) {
        bcol[j] = bias ? __ldg(&bias[col0 + j]) : 0.f;
        dcol[j] = degvec ? __ldg(&degvec[col0 + j]) : 0.f;
    }
#pragma unroll
    for (int rr = 0; rr < 8; rr++) {
        int row = row0 + rowt + rr;
        if (row < N) {
            float dg = deg ? deg[row] : 0.f;
            float o[8];
#pragma unroll
            for (int cp = 0; cp < 4; cp++) unpack2(acc[rr][cp], o[2 * cp], o[2 * cp + 1]);
#pragma unroll
            for (int j = 0; j < 8; j++) {
                float vv2 = o[j] + bcol[j] + dg * dcol[j];
                if (ACT == 1) vv2 = vv2 * fast_sigmoid(vv2);
                o[j] = vv2;
            }
            float4* op = (float4*)(out + (size_t)row * F + col0);
            op[0] = make_float4(o[0], o[1], o[2], o[3]);
            op[1] = make_float4(o[4], o[5], o[6], o[7]);
        }
    }
}

// ---------------------------------------------------------------------------
// Residual + LayerNorm: xout = LN(P + x)
__global__ void __launch_bounds__(256)
ln_kernel(const float* __restrict__ P, const float* __restrict__ x,
          const float* __restrict__ gamma, const float* __restrict__ beta,
          float* __restrict__ xout, int N) {
    int row = blockIdx.x * 8 + (threadIdx.x >> 5);
    int lane = threadIdx.x & 31;
    if (row >= N) return;
    float4 p = ((const float4*)P)[(size_t)row * 32 + lane];
    float4 xv = ((const float4*)x)[(size_t)row * 32 + lane];
    float4 pre = make_float4(p.x + xv.x, p.y + xv.y, p.z + xv.z, p.w + xv.w);
    float s = pre.x + pre.y + pre.z + pre.w;
    float s2 = pre.x * pre.x + pre.y * pre.y + pre.z * pre.z + pre.w * pre.w;
#pragma unroll
    for (int o = 16; o > 0; o >>= 1) {
        s  += __shfl_xor_sync(0xffffffffu, s, o);
        s2 += __shfl_xor_sync(0xffffffffu, s2, o);
    }
    float mean = s * (1.f / F);
    float ri = rsqrtf(s2 * (1.f / F) - mean * mean + LN_EPS);
    float4 g = ((const float4*)gamma)[lane];
    float4 b = ((const float4*)beta)[lane];
    float4 o;
    o.x = g.x * (pre.x - mean) * ri + b.x;
    o.y = g.y * (pre.y - mean) * ri + b.y;
    o.z = g.z * (pre.z - mean) * ri + b.z;
    o.w = g.w * (pre.w - mean) * ri + b.w;
    ((float4*)xout)[(size_t)row * 32 + lane] = o;
}

// ---------------------------------------------------------------------------
extern "C" void kernel_launch(void* const* d_in, const int* in_sizes, int n_in,
                              void* d_out, int out_size) {
    const float* x     = (const float*)d_in[0];
    const float* pos   = (const float*)d_in[1];
    const void*  ei    = d_in[2];
    const float* ew1   = (const float*)d_in[3];
    const float* eb1   = (const float*)d_in[4];
    const float* ew2   = (const float*)d_in[5];
    const float* eb2   = (const float*)d_in[6];
    const float* nw1   = (const float*)d_in[7];
    const float* nb1   = (const float*)d_in[8];
    const float* nw2   = (const float*)d_in[9];
    const float* nb2   = (const float*)d_in[10];
    const float* cw    = (const float*)d_in[11];
    const float* cb    = (const float*)d_in[12];
    const float* gamma = (const float*)d_in[13];
    const float* beta  = (const float*)d_in[14];

    int N = in_sizes[0] / F;
    int E = in_sizes[2] / 2;

    float* xout = (float*)d_out;
    float* pout = (float*)d_out + (size_t)N * F;

    float* XA;   cudaGetSymbolAddress((void**)&XA,   g_XA);
    float* XB;   cudaGetSymbolAddress((void**)&XB,   g_XB);
    float* AGGS; cudaGetSymbolAddress((void**)&AGGS, g_AGGS);
    float* DEG;  cudaGetSymbolAddress((void**)&DEG,  g_DEG);

    cudaFuncSetAttribute(gemm_rt<0>, cudaFuncAttributeMaxDynamicSharedMemorySize, SM_RT_TOTAL);
    cudaFuncSetAttribute(gemm_rt<1>, cudaFuncAttributeMaxDynamicSharedMemorySize, SM_RT_TOTAL);

    int tcb = (N + 127) / 128;
    int eb256 = (E + 255) / 256;

    detect_kernel<<<1, 256>>>(ei, E, N);
    prep_vc<<<1, 128>>>(ew2, cw, eb2, cb);

    // CSR build (independent of GEMMs)
    zero_cnt<<<(N + 255) / 256, 256>>>(N);
    hist_kernel<<<eb256, 256>>>(ei, E);
    scan_kernel<<<1, 1024>>>(N);
    scatter_kernel<<<eb256, 256>>>(ei, E);

    // XA = x @ W1a + eb1 AND XB = x @ W1b — one merged launch
    gemm_rt<0><<<dim3(tcb, 2), 256, SM_RT_TOTAL>>>(
        x, ew1, eb1, XA, ew1 + 128 * F, nullptr, XB, nullptr, nullptr, N);

    // Gather: agg rows + degree + pos_out (no atomics)
    gather_kernel<<<(N + 7) / 8, 256>>>(pos, ew1, pout, N);

    // AGG = AGGS @ ew2 + deg*eb2  -> XA
    gemm_rt<0><<<tcb, 256, SM_RT_TOTAL>>>(AGGS, ew2, nullptr, XA,
                                          nullptr, nullptr, nullptr, DEG, eb2, N);
    // H = silu(AGG @ nw1 + nb1)   -> XB
    gemm_rt<1><<<tcb, 256, SM_RT_TOTAL>>>(XA, nw1, nb1, XB,
                                          nullptr, nullptr, nullptr, nullptr, nullptr, N);
    // P = H @ nw2 + nb2           -> AGGS (reuse)
    gemm_rt<0><<<tcb, 256, SM_RT_TOTAL>>>(XB, nw2, nb2, AGGS,
                                          nullptr, nullptr, nullptr, nullptr, nullptr, N);
    // x_out = LN(x + P)
    ln_kernel<<<(N + 7) / 8, 256>>>(AGGS, x, gamma, beta, xout, N);
}

// round 10
// speedup vs baseline: 1.2204x; 1.1484x over previous
#include <cuda_runtime.h>
#include <cuda_bf16.h>
#include <math.h>
#include <stdint.h>

#define NMAX 50048
#define F 128
#define LN_EPS 1e-5f

// ---------------------------------------------------------------------------
// Scratch (device globals — no allocation allowed)
__device__ float g_XA[NMAX * F];
__device__ float g_XB[NMAX * F];
__device__ float g_AGGS[NMAX * F];
__device__ float g_DELTA[NMAX * 3];
__device__ float g_DEG[NMAX];
__device__ float g_V[F];
__device__ float g_C0;
__device__ int   g_IS64;

// ---------------------------------------------------------------------------
#define FFMA2(acc, a, b) \
    asm("fma.rn.f32x2 %0, %1, %2, %0;" : "+l"(acc) : "l"(a), "l"(b))
__device__ __forceinline__ unsigned long long pack2(float v) {
    unsigned long long r;
    unsigned int u = __float_as_uint(v);
    asm("mov.b64 %0, {%1, %1};" : "=l"(r) : "r"(u));
    return r;
}
__device__ __forceinline__ void unpack2(unsigned long long p, float& lo, float& hi) {
    unsigned int a, b;
    asm("mov.b64 {%0, %1}, %2;" : "=r"(a), "=r"(b) : "l"(p));
    lo = __uint_as_float(a);
    hi = __uint_as_float(b);
}
__device__ __forceinline__ uint32_t smem_u32(const void* p) {
    uint32_t a;
    asm("{ .reg .u64 t; cvta.to.shared.u64 t, %1; cvt.u32.u64 %0, t; }"
        : "=r"(a) : "l"(p));
    return a;
}
#define CP_ASYNC16(dst, src) \
    asm volatile("cp.async.cg.shared.global [%0], [%1], 16;" :: "r"(dst), "l"(src))
#define CP_COMMIT() asm volatile("cp.async.commit_group;" ::: "memory")
#define CP_WAIT0()  asm volatile("cp.async.wait_group 0;" ::: "memory")

__device__ __forceinline__ float fast_sigmoid(float p) {
    return __fdividef(1.f, 1.f + __expf(-p));
}
__device__ __forceinline__ float fast_tanh(float x) {
    // tanh(x) = 1 - 2/(e^{2x}+1); 2 MUFU ops instead of tanhf's long routine
    return 1.f - __fdividef(2.f, __expf(2.f * x) + 1.f);
}

// ---------------------------------------------------------------------------
// Parallel dtype detect
__global__ void detect_kernel(const void* ei, int E, int N) {
    __shared__ int bad;
    if (threadIdx.x == 0) bad = 0;
    __syncthreads();
    int cnt = (2 * E < 256) ? 2 * E : 256;
    if ((int)threadIdx.x < cnt) {
        long long v = ((const long long*)ei)[threadIdx.x];
        if (v < 0 || v >= N) bad = 1;
    }
    __syncthreads();
    if (threadIdx.x == 0) g_IS64 = !bad;
}

__global__ void prep_vc(const float* __restrict__ ew2, const float* __restrict__ cw,
                        const float* __restrict__ eb2, const float* __restrict__ cb) {
    int t = threadIdx.x;
    float s = 0.f;
    for (int o = 0; o < F; o++) s += ew2[t * F + o] * cw[o];
    g_V[t] = s;
    if (t == 0) {
        float c = cb[0];
        for (int o = 0; o < F; o++) c += eb2[o] * cw[o];
        g_C0 = c;
    }
}

__global__ void zero_kernel(int N) {
    int n4 = N * 32;
    float4 z4 = make_float4(0.f, 0.f, 0.f, 0.f);
    float4* a4 = (float4*)g_AGGS;
    int stride = gridDim.x * blockDim.x;
    for (int i = blockIdx.x * blockDim.x + threadIdx.x; i < n4; i += stride) a4[i] = z4;
    for (int i = blockIdx.x * blockDim.x + threadIdx.x; i < N * 3; i += stride) g_DELTA[i] = 0.f;
    for (int i = blockIdx.x * blockDim.x + threadIdx.x; i < N; i += stride) g_DEG[i] = 0.f;
}

// ---------------------------------------------------------------------------
// Edge kernel: one warp per edge, v4 RED scatter (R6 structure + fast math).
__global__ void __launch_bounds__(256)
edge_kernel(const void* __restrict__ ei_raw, const float* __restrict__ pos,
            const float* __restrict__ ew1, int E, int N) {
    int gw = (blockIdx.x * blockDim.x + threadIdx.x) >> 5;
    int lane = threadIdx.x & 31;
    if (gw >= E) return;

    int row, col;
    if (g_IS64) {
        const long long* ei = (const long long*)ei_raw;
        row = (int)ei[gw];
        col = (int)ei[(size_t)E + gw];
    } else {
        const int* ei = (const int*)ei_raw;
        row = ei[gw];
        col = ei[E + gw];
    }

    float dx = pos[row * 3 + 0] - pos[col * 3 + 0];
    float dy = pos[row * 3 + 1] - pos[col * 3 + 1];
    float dz = pos[row * 3 + 2] - pos[col * 3 + 2];
    float dist2 = dx * dx + dy * dy + dz * dz;

    const float4* XA4 = (const float4*)g_XA;
    const float4* XB4 = (const float4*)g_XB;
    float4 a = XA4[(size_t)row * 32 + lane];
    float4 b = XB4[(size_t)col * 32 + lane];
    float4 w = __ldg((const float4*)(ew1 + 256 * F) + lane);

    float p0 = a.x + b.x + dist2 * w.x;
    float p1 = a.y + b.y + dist2 * w.y;
    float p2 = a.z + b.z + dist2 * w.z;
    float p3 = a.w + b.w + dist2 * w.w;

    float s0 = p0 * fast_sigmoid(p0);
    float s1 = p1 * fast_sigmoid(p1);
    float s2 = p2 * fast_sigmoid(p2);
    float s3 = p3 * fast_sigmoid(p3);

    float* aggp = g_AGGS + (size_t)row * F + lane * 4;
    asm volatile("red.global.add.v4.f32 [%0], {%1, %2, %3, %4};"
                 :: "l"(aggp), "f"(s0), "f"(s1), "f"(s2), "f"(s3) : "memory");

    float4 vv = ((const float4*)g_V)[lane];
    float d = s0 * vv.x + s1 * vv.y + s2 * vv.z + s3 * vv.w;
#pragma unroll
    for (int o = 16; o > 0; o >>= 1) d += __shfl_xor_sync(0xffffffffu, d, o);

    if (lane == 0) {
        float sc = fast_tanh(d + g_C0);
        atomicAdd(&g_DELTA[row * 3 + 0], sc * dx);
        atomicAdd(&g_DELTA[row * 3 + 1], sc * dy);
        atomicAdd(&g_DELTA[row * 3 + 2], sc * dz);
        atomicAdd(&g_DEG[row], 1.0f);
    }
}

// ---------------------------------------------------------------------------
// Pipelined register-tiled GEMM (R6 structure; __fdividef silu)
#define AS_STRIDE 132
#define WS_BYTES  16384
#define AS_BYTES  16896
#define SM_AS0    (2 * WS_BYTES)
#define SM_RT_TOTAL (2 * WS_BYTES + 2 * AS_BYTES)

template <int ACT>
__global__ void __launch_bounds__(256, 2)
gemm_rt(const float* __restrict__ A,
        const float* __restrict__ W0, const float* __restrict__ bias0,
        float* __restrict__ out0,
        const float* __restrict__ W1, const float* __restrict__ bias1,
        float* __restrict__ out1,
        const float* __restrict__ deg, const float* __restrict__ degvec, int N) {
    extern __shared__ char smem[];

    const float* W = W0;
    const float* bias = bias0;
    float* out = out0;
    if (blockIdx.y == 1) { W = W1; bias = bias1; out = out1; }

    int t = threadIdx.x;
    int lane = t & 31, w = t >> 5;
    int txl = lane & 3, tyl = lane >> 2;
    int wx = w & 3, wy = w >> 2;
    int col0 = (wx * 4 + txl) * 8;
    int rowt = (wy * 8 + tyl) * 8;
    int row0 = blockIdx.x * 128;

    uint32_t sb = smem_u32(smem);

    int arl = (w & 3) * 32 + lane;
    int kh  = (w >> 2) * 16;
    int arow = row0 + arl;
    const float4* Abase = (const float4*)(A + (size_t)arow * F);

    int wk = t >> 3, wcol = (t & 7) * 16;

    unsigned long long acc[8][4];
#pragma unroll
    for (int r = 0; r < 8; r++)
#pragma unroll
        for (int c = 0; c < 4; c++) acc[r][c] = 0ull;

    float4 v[4];

    {
        const float* wsrc = W + (size_t)wk * F + wcol;
        uint32_t wdst = sb + (uint32_t)(wk * F + wcol) * 4;
#pragma unroll
        for (int q = 0; q < 4; q++) CP_ASYNC16(wdst + q * 16, wsrc + q * 4);
        CP_COMMIT();
        if (arow < N) {
#pragma unroll
            for (int q = 0; q < 4; q++) v[q] = __ldg(&Abase[(kh >> 2) + q]);
        } else {
#pragma unroll
            for (int q = 0; q < 4; q++) v[q] = make_float4(0.f, 0.f, 0.f, 0.f);
        }
        float* As0 = (float*)(smem + SM_AS0);
#pragma unroll
        for (int q = 0; q < 4; q++) {
            float vals[4] = {v[q].x, v[q].y, v[q].z, v[q].w};
#pragma unroll
            for (int e = 0; e < 4; e++)
                As0[(kh + q * 4 + e) * AS_STRIDE + arl] = vals[e];
        }
        CP_WAIT0();
    }
    __syncthreads();

#pragma unroll 1
    for (int c = 0; c < 4; c++) {
        int cb = c & 1, nb = (c + 1) & 1;
        float* Ws = (float*)(smem + cb * WS_BYTES);
        float* As = (float*)(smem + SM_AS0 + cb * AS_BYTES);

        if (c < 3) {
            const float* wsrc = W + (size_t)((c + 1) * 32 + wk) * F + wcol;
            uint32_t wdst = sb + (uint32_t)nb * WS_BYTES + (uint32_t)(wk * F + wcol) * 4;
#pragma unroll
            for (int q = 0; q < 4; q++) CP_ASYNC16(wdst + q * 16, wsrc + q * 4);
            CP_COMMIT();
            if (arow < N) {
                int kb = ((c + 1) * 32 + kh) >> 2;
#pragma unroll
                for (int q = 0; q < 4; q++) v[q] = __ldg(&Abase[kb + q]);
            }
        }

#pragma unroll
        for (int kk = 0; kk < 32; kk++) {
            float4 al = *(const float4*)&As[kk * AS_STRIDE + rowt];
            float4 ah = *(const float4*)&As[kk * AS_STRIDE + rowt + 4];
            unsigned long long a0 = pack2(al.x), a1 = pack2(al.y);
            unsigned long long a2 = pack2(al.z), a3 = pack2(al.w);
            unsigned long long a4 = pack2(ah.x), a5 = pack2(ah.y);
            unsigned long long a6 = pack2(ah.z), a7 = pack2(ah.w);
            ulonglong2 bv0 = *(const ulonglong2*)&Ws[kk * F + col0];
            ulonglong2 bv1 = *(const ulonglong2*)&Ws[kk * F + col0 + 4];
            FFMA2(acc[0][0], a0, bv0.x); FFMA2(acc[0][1], a0, bv0.y);
            FFMA2(acc[0][2], a0, bv1.x); FFMA2(acc[0][3], a0, bv1.y);
            FFMA2(acc[1][0], a1, bv0.x); FFMA2(acc[1][1], a1, bv0.y);
            FFMA2(acc[1][2], a1, bv1.x); FFMA2(acc[1][3], a1, bv1.y);
            FFMA2(acc[2][0], a2, bv0.x); FFMA2(acc[2][1], a2, bv0.y);
            FFMA2(acc[2][2], a2, bv1.x); FFMA2(acc[2][3], a2, bv1.y);
            FFMA2(acc[3][0], a3, bv0.x); FFMA2(acc[3][1], a3, bv0.y);
            FFMA2(acc[3][2], a3, bv1.x); FFMA2(acc[3][3], a3, bv1.y);
            FFMA2(acc[4][0], a4, bv0.x); FFMA2(acc[4][1], a4, bv0.y);
            FFMA2(acc[4][2], a4, bv1.x); FFMA2(acc[4][3], a4, bv1.y);
            FFMA2(acc[5][0], a5, bv0.x); FFMA2(acc[5][1], a5, bv0.y);
            FFMA2(acc[5][2], a5, bv1.x); FFMA2(acc[5][3], a5, bv1.y);
            FFMA2(acc[6][0], a6, bv0.x); FFMA2(acc[6][1], a6, bv0.y);
            FFMA2(acc[6][2], a6, bv1.x); FFMA2(acc[6][3], a6, bv1.y);
            FFMA2(acc[7][0], a7, bv0.x); FFMA2(acc[7][1], a7, bv0.y);
            FFMA2(acc[7][2], a7, bv1.x); FFMA2(acc[7][3], a7, bv1.y);
        }

        if (c < 3) {
            float* Asn = (float*)(smem + SM_AS0 + nb * AS_BYTES);
            if (arow >= N) {
#pragma unroll
                for (int q = 0; q < 4; q++) v[q] = make_float4(0.f, 0.f, 0.f, 0.f);
            }
#pragma unroll
            for (int q = 0; q < 4; q++) {
                float vals[4] = {v[q].x, v[q].y, v[q].z, v[q].w};
#pragma unroll
                for (int e = 0; e < 4; e++)
                    Asn[(kh + q * 4 + e) * AS_STRIDE + arl] = vals[e];
            }
            CP_WAIT0();
        }
        __syncthreads();
    }

    float bcol[8], dcol[8];
#pragma unroll
    for (int j = 0; j < 8; j++) {
        bcol[j] = bias ? __ldg(&bias[col0 + j]) : 0.f;
        dcol[j] = degvec ? __ldg(&degvec[col0 + j]) : 0.f;
    }
#pragma unroll
    for (int rr = 0; rr < 8; rr++) {
        int row = row0 + rowt + rr;
        if (row < N) {
            float dg = deg ? deg[row] : 0.f;
            float o[8];
#pragma unroll
            for (int cp = 0; cp < 4; cp++) unpack2(acc[rr][cp], o[2 * cp], o[2 * cp + 1]);
#pragma unroll
            for (int j = 0; j < 8; j++) {
                float vv2 = o[j] + bcol[j] + dg * dcol[j];
                if (ACT == 1) vv2 = vv2 * fast_sigmoid(vv2);
                o[j] = vv2;
            }
            float4* op = (float4*)(out + (size_t)row * F + col0);
            op[0] = make_float4(o[0], o[1], o[2], o[3]);
            op[1] = make_float4(o[4], o[5], o[6], o[7]);
        }
    }
}

// ---------------------------------------------------------------------------
// Residual + LayerNorm: xout = LN(P + x)
__global__ void __launch_bounds__(256)
ln_kernel(const float* __restrict__ P, const float* __restrict__ x,
          const float* __restrict__ gamma, const float* __restrict__ beta,
          float* __restrict__ xout, int N) {
    int row = blockIdx.x * 8 + (threadIdx.x >> 5);
    int lane = threadIdx.x & 31;
    if (row >= N) return;
    float4 p = ((const float4*)P)[(size_t)row * 32 + lane];
    float4 xv = ((const float4*)x)[(size_t)row * 32 + lane];
    float4 pre = make_float4(p.x + xv.x, p.y + xv.y, p.z + xv.z, p.w + xv.w);
    float s = pre.x + pre.y + pre.z + pre.w;
    float s2 = pre.x * pre.x + pre.y * pre.y + pre.z * pre.z + pre.w * pre.w;
#pragma unroll
    for (int o = 16; o > 0; o >>= 1) {
        s  += __shfl_xor_sync(0xffffffffu, s, o);
        s2 += __shfl_xor_sync(0xffffffffu, s2, o);
    }
    float mean = s * (1.f / F);
    float ri = rsqrtf(s2 * (1.f / F) - mean * mean + LN_EPS);
    float4 g = ((const float4*)gamma)[lane];
    float4 b = ((const float4*)beta)[lane];
    float4 o;
    o.x = g.x * (pre.x - mean) * ri + b.x;
    o.y = g.y * (pre.y - mean) * ri + b.y;
    o.z = g.z * (pre.z - mean) * ri + b.z;
    o.w = g.w * (pre.w - mean) * ri + b.w;
    ((float4*)xout)[(size_t)row * 32 + lane] = o;
}

__global__ void pos_kernel(const float* __restrict__ pos, float* __restrict__ out, int N) {
    int i = blockIdx.x * blockDim.x + threadIdx.x;
    if (i < N * 3) out[i] = pos[i] + g_DELTA[i];
}

// ---------------------------------------------------------------------------
extern "C" void kernel_launch(void* const* d_in, const int* in_sizes, int n_in,
                              void* d_out, int out_size) {
    const float* x     = (const float*)d_in[0];
    const float* pos   = (const float*)d_in[1];
    const void*  ei    = d_in[2];
    const float* ew1   = (const float*)d_in[3];
    const float* eb1   = (const float*)d_in[4];
    const float* ew2   = (const float*)d_in[5];
    const float* eb2   = (const float*)d_in[6];
    const float* nw1   = (const float*)d_in[7];
    const float* nb1   = (const float*)d_in[8];
    const float* nw2   = (const float*)d_in[9];
    const float* nb2   = (const float*)d_in[10];
    const float* cw    = (const float*)d_in[11];
    const float* cb    = (const float*)d_in[12];
    const float* gamma = (const float*)d_in[13];
    const float* beta  = (const float*)d_in[14];

    int N = in_sizes[0] / F;
    int E = in_sizes[2] / 2;

    float* xout = (float*)d_out;
    float* pout = (float*)d_out + (size_t)N * F;

    float* XA;   cudaGetSymbolAddress((void**)&XA,   g_XA);
    float* XB;   cudaGetSymbolAddress((void**)&XB,   g_XB);
    float* AGGS; cudaGetSymbolAddress((void**)&AGGS, g_AGGS);
    float* DEG;  cudaGetSymbolAddress((void**)&DEG,  g_DEG);

    cudaFuncSetAttribute(gemm_rt<0>, cudaFuncAttributeMaxDynamicSharedMemorySize, SM_RT_TOTAL);
    cudaFuncSetAttribute(gemm_rt<1>, cudaFuncAttributeMaxDynamicSharedMemorySize, SM_RT_TOTAL);

    int tcb = (N + 127) / 128;

    detect_kernel<<<1, 256>>>(ei, E, N);
    prep_vc<<<1, 128>>>(ew2, cw, eb2, cb);
    zero_kernel<<<2048, 256>>>(N);

    // XA = x @ W1a + eb1 AND XB = x @ W1b — one merged launch
    gemm_rt<0><<<dim3(tcb, 2), 256, SM_RT_TOTAL>>>(
        x, ew1, eb1, XA, ew1 + 128 * F, nullptr, XB, nullptr, nullptr, N);

    // Edge stage
    int eblocks = (E * 32 + 255) / 256;
    edge_kernel<<<eblocks, 256>>>(ei, pos, ew1, E, N);

    // AGG = AGGS @ ew2 + deg*eb2  -> XA
    gemm_rt<0><<<tcb, 256, SM_RT_TOTAL>>>(AGGS, ew2, nullptr, XA,
                                          nullptr, nullptr, nullptr, DEG, eb2, N);
    // H = silu(AGG @ nw1 + nb1)   -> XB
    gemm_rt<1><<<tcb, 256, SM_RT_TOTAL>>>(XA, nw1, nb1, XB,
                                          nullptr, nullptr, nullptr, nullptr, nullptr, N);
    // P = H @ nw2 + nb2           -> AGGS (reuse)
    gemm_rt<0><<<tcb, 256, SM_RT_TOTAL>>>(XB, nw2, nb2, AGGS,
                                          nullptr, nullptr, nullptr, nullptr, nullptr, N);
    // x_out = LN(x + P)
    ln_kernel<<<(N + 7) / 8, 256>>>(AGGS, x, gamma, beta, xout, N);
    // pos_out
    pos_kernel<<<(N * 3 + 255) / 256, 256>>>(pos, pout, N);
}